// round 7
// baseline (speedup 1.0000x reference)
#include <cuda_runtime.h>
#include <cuda_fp16.h>
#include <math.h>

#define NN 100000
#define NE 3200000
#define NG 64
#define D 32
#define INF 128
#define NPAD 102400   // 1024 threads * 100 counters

// ---- scratch ----
__device__ __half g_rhsH[NN * D];   // fp16 gather buffer
__device__ float  g_self[NN * D];
__device__ float  g_h[NN * D];
__device__ float  g_pool[NG * D];
__device__ int    g_counts[NPAD];
__device__ int    g_offs[NPAD + 1];
__device__ int    g_cursor[NPAD];
__device__ int    g_csrc[NE];

// ------------------------------------------------------------------
__global__ void zero_kernel() {
    int i = blockIdx.x * blockDim.x + threadIdx.x;
    if (i < NPAD) g_counts[i] = 0;
    if (i < NG * D) g_pool[i] = 0.f;
}

__global__ void hist_kernel(const int* __restrict__ dst) {
    int i = blockIdx.x * blockDim.x + threadIdx.x;
    int b = i * 4;
    if (b < NE) {
        int4 d = *(const int4*)&dst[b];
        atomicAdd(&g_counts[d.x], 1);
        atomicAdd(&g_counts[d.y], 1);
        atomicAdd(&g_counts[d.z], 1);
        atomicAdd(&g_counts[d.w], 1);
    }
}

// single-block scan: 1024 threads x 100 contiguous counters each
__global__ void __launch_bounds__(1024) scan_all() {
    const int CH = 100;
    int tid = threadIdx.x;
    int lane = tid & 31, wid = tid >> 5;
    int base = tid * CH;
    int s = 0;
#pragma unroll
    for (int i = 0; i < CH; i += 4) {
        int4 v = *(const int4*)&g_counts[base + i];
        s += v.x + v.y + v.z + v.w;
    }
    int pre = s;
#pragma unroll
    for (int dd = 1; dd < 32; dd <<= 1) {
        int t = __shfl_up_sync(0xffffffffu, pre, dd);
        if (lane >= dd) pre += t;
    }
    __shared__ int wsum[32];
    if (lane == 31) wsum[wid] = pre;
    __syncthreads();
    if (wid == 0) {
        int v = wsum[lane];
        int p = v;
#pragma unroll
        for (int dd = 1; dd < 32; dd <<= 1) {
            int t = __shfl_up_sync(0xffffffffu, p, dd);
            if (lane >= dd) p += t;
        }
        wsum[lane] = p - v;
    }
    __syncthreads();
    int run = wsum[wid] + (pre - s);
#pragma unroll
    for (int i = 0; i < CH; i += 4) {
        int4 c = *(const int4*)&g_counts[base + i];
        int4 o;
        o.x = run; run += c.x;
        o.y = run; run += c.y;
        o.z = run; run += c.z;
        o.w = run; run += c.w;
        *(int4*)&g_offs[base + i]   = o;
        *(int4*)&g_cursor[base + i] = o;
    }
}

__global__ void scatter_kernel(const int* __restrict__ src, const int* __restrict__ dst) {
    int i = blockIdx.x * blockDim.x + threadIdx.x;
    int b = i * 4;
    if (b < NE) {
        int4 s4 = *(const int4*)&src[b];
        int4 d4 = *(const int4*)&dst[b];
        int p;
        p = atomicAdd(&g_cursor[d4.x], 1); g_csrc[p] = s4.x;
        p = atomicAdd(&g_cursor[d4.y], 1); g_csrc[p] = s4.y;
        p = atomicAdd(&g_cursor[d4.z], 1); g_csrc[p] = s4.z;
        p = atomicAdd(&g_cursor[d4.w], 1); g_csrc[p] = s4.w;
    }
}

// ------------------------------------------------------------------
// Store helper: 16 fp32 accumulators -> 16 fp16 at rhsH[n*D + c0] (32 bytes!)
__device__ __forceinline__ void store_rhs_fp16(__half* dstp, const float* a) {
    __align__(16) __half2 hp[8];
#pragma unroll
    for (int j = 0; j < 8; j++)
        hp[j] = __floats2half2_rn(a[2 * j], a[2 * j + 1]);
    *(uint4*)&dstp[0] = *(uint4*)&hp[0];   // halves 0..7
    *(uint4*)&dstp[8] = *(uint4*)&hp[4];   // halves 8..15
}

// Layer 0: rhsH = fp16(x@Wn0), self = x@Ws0  (register blocked).
__global__ void __launch_bounds__(64) gemm0_kernel(const float* __restrict__ x,
                                                   const float* __restrict__ Wn0,
                                                   const float* __restrict__ Ws0) {
    __shared__ float Wsh[INF][64];
    __shared__ float xs[64][33];
    int tid = threadIdx.x;
    for (int idx = tid; idx < INF * D; idx += 64) {
        int k = idx >> 5, c = idx & 31;
        Wsh[k][c]      = Wn0[idx];
        Wsh[k][c + 32] = Ws0[idx];
    }
    int n0 = blockIdx.x * 64;
    int ng = tid >> 2, cg = tid & 3;
    int c0 = cg * 16;
    float acc[4][16];
#pragma unroll
    for (int i = 0; i < 4; i++)
#pragma unroll
        for (int j = 0; j < 16; j++) acc[i][j] = 0.f;

    for (int kt = 0; kt < 4; kt++) {
        __syncthreads();
        for (int idx = tid; idx < 64 * 32; idx += 64) {
            int nl = idx >> 5, j = idx & 31;
            int n = n0 + nl;
            xs[nl][j] = (n < NN) ? x[n * INF + kt * 32 + j] : 0.f;
        }
        __syncthreads();
#pragma unroll 4
        for (int k = 0; k < 32; k++) {
            float xv[4];
#pragma unroll
            for (int i = 0; i < 4; i++) xv[i] = xs[ng * 4 + i][k];
            const float* wrow = &Wsh[kt * 32 + k][c0];
            float4 w0 = *(const float4*)&wrow[0];
            float4 w1 = *(const float4*)&wrow[4];
            float4 w2 = *(const float4*)&wrow[8];
            float4 w3 = *(const float4*)&wrow[12];
#pragma unroll
            for (int i = 0; i < 4; i++) {
                float xi = xv[i];
                acc[i][0]  = fmaf(xi, w0.x, acc[i][0]);
                acc[i][1]  = fmaf(xi, w0.y, acc[i][1]);
                acc[i][2]  = fmaf(xi, w0.z, acc[i][2]);
                acc[i][3]  = fmaf(xi, w0.w, acc[i][3]);
                acc[i][4]  = fmaf(xi, w1.x, acc[i][4]);
                acc[i][5]  = fmaf(xi, w1.y, acc[i][5]);
                acc[i][6]  = fmaf(xi, w1.z, acc[i][6]);
                acc[i][7]  = fmaf(xi, w1.w, acc[i][7]);
                acc[i][8]  = fmaf(xi, w2.x, acc[i][8]);
                acc[i][9]  = fmaf(xi, w2.y, acc[i][9]);
                acc[i][10] = fmaf(xi, w2.z, acc[i][10]);
                acc[i][11] = fmaf(xi, w2.w, acc[i][11]);
                acc[i][12] = fmaf(xi, w3.x, acc[i][12]);
                acc[i][13] = fmaf(xi, w3.y, acc[i][13]);
                acc[i][14] = fmaf(xi, w3.z, acc[i][14]);
                acc[i][15] = fmaf(xi, w3.w, acc[i][15]);
            }
        }
    }
#pragma unroll
    for (int i = 0; i < 4; i++) {
        int n = n0 + ng * 4 + i;
        if (n >= NN) break;
        if (cg < 2) {
            store_rhs_fp16(&g_rhsH[n * D + c0], acc[i]);
        } else {
            float* dstp = &g_self[n * D + (c0 - 32)];
#pragma unroll
            for (int j = 0; j < 4; j++) {
                float4 f = make_float4(acc[i][4 * j], acc[i][4 * j + 1],
                                       acc[i][4 * j + 2], acc[i][4 * j + 3]);
                *(float4*)&dstp[4 * j] = f;
            }
        }
    }
}

// Layers 1..3: rhsH = fp16(h@Wn_l), self = h@Ws_l  (register blocked, K=32).
__global__ void __launch_bounds__(64) gemm_small_kernel(const float* __restrict__ Wn_l,
                                                        const float* __restrict__ Ws_l) {
    __shared__ float Wsh[D][64];
    __shared__ float xs[64][33];
    int tid = threadIdx.x;
    for (int idx = tid; idx < D * D; idx += 64) {
        int k = idx >> 5, c = idx & 31;
        Wsh[k][c]      = Wn_l[idx];
        Wsh[k][c + 32] = Ws_l[idx];
    }
    int n0 = blockIdx.x * 64;
    for (int idx = tid; idx < 64 * 32; idx += 64) {
        int nl = idx >> 5, j = idx & 31;
        int n = n0 + nl;
        xs[nl][j] = (n < NN) ? g_h[n * D + j] : 0.f;
    }
    __syncthreads();
    int ng = tid >> 2, cg = tid & 3;
    int c0 = cg * 16;
    float acc[4][16];
#pragma unroll
    for (int i = 0; i < 4; i++)
#pragma unroll
        for (int j = 0; j < 16; j++) acc[i][j] = 0.f;

#pragma unroll 4
    for (int k = 0; k < 32; k++) {
        float xv[4];
#pragma unroll
        for (int i = 0; i < 4; i++) xv[i] = xs[ng * 4 + i][k];
        const float* wrow = &Wsh[k][c0];
        float4 w0 = *(const float4*)&wrow[0];
        float4 w1 = *(const float4*)&wrow[4];
        float4 w2 = *(const float4*)&wrow[8];
        float4 w3 = *(const float4*)&wrow[12];
#pragma unroll
        for (int i = 0; i < 4; i++) {
            float xi = xv[i];
            acc[i][0]  = fmaf(xi, w0.x, acc[i][0]);
            acc[i][1]  = fmaf(xi, w0.y, acc[i][1]);
            acc[i][2]  = fmaf(xi, w0.z, acc[i][2]);
            acc[i][3]  = fmaf(xi, w0.w, acc[i][3]);
            acc[i][4]  = fmaf(xi, w1.x, acc[i][4]);
            acc[i][5]  = fmaf(xi, w1.y, acc[i][5]);
            acc[i][6]  = fmaf(xi, w1.z, acc[i][6]);
            acc[i][7]  = fmaf(xi, w1.w, acc[i][7]);
            acc[i][8]  = fmaf(xi, w2.x, acc[i][8]);
            acc[i][9]  = fmaf(xi, w2.y, acc[i][9]);
            acc[i][10] = fmaf(xi, w2.z, acc[i][10]);
            acc[i][11] = fmaf(xi, w2.w, acc[i][11]);
            acc[i][12] = fmaf(xi, w3.x, acc[i][12]);
            acc[i][13] = fmaf(xi, w3.y, acc[i][13]);
            acc[i][14] = fmaf(xi, w3.z, acc[i][14]);
            acc[i][15] = fmaf(xi, w3.w, acc[i][15]);
        }
    }
#pragma unroll
    for (int i = 0; i < 4; i++) {
        int n = n0 + ng * 4 + i;
        if (n >= NN) break;
        if (cg < 2) {
            store_rhs_fp16(&g_rhsH[n * D + c0], acc[i]);
        } else {
            float* dstp = &g_self[n * D + (c0 - 32)];
#pragma unroll
            for (int j = 0; j < 4; j++) {
                float4 f = make_float4(acc[i][4 * j], acc[i][4 * j + 1],
                                       acc[i][4 * j + 2], acc[i][4 * j + 3]);
                *(float4*)&dstp[4 * j] = f;
            }
        }
    }
}

// ------------------------------------------------------------------
// Aggregation: warp per node, lane = dim; fp16 gather rows (64 B/warp-load).
__global__ void __launch_bounds__(256) agg_kernel(const float* __restrict__ bn) {
    int w = (blockIdx.x * blockDim.x + threadIdx.x) >> 5;
    int lane = threadIdx.x & 31;
    if (w >= NN) return;
    int beg = g_offs[w], end = g_offs[w + 1];
    float acc = g_self[w * D + lane] + bn[lane];
    int e = beg;
    for (; e + 4 <= end; e += 4) {
        int s0 = g_csrc[e], s1 = g_csrc[e + 1], s2 = g_csrc[e + 2], s3 = g_csrc[e + 3];
        float v0 = __half2float(g_rhsH[s0 * D + lane]);
        float v1 = __half2float(g_rhsH[s1 * D + lane]);
        float v2 = __half2float(g_rhsH[s2 * D + lane]);
        float v3 = __half2float(g_rhsH[s3 * D + lane]);
        acc += v0; acc += v1; acc += v2; acc += v3;
    }
    for (; e < end; e++) acc += __half2float(g_rhsH[g_csrc[e] * D + lane]);
    g_h[w * D + lane] = fmaxf(acc, 0.f);
}

// ------------------------------------------------------------------
__global__ void __launch_bounds__(256) pool_kernel(const int* __restrict__ gid) {
    __shared__ float ps[NG * D];
    int tid = threadIdx.x;
    for (int i = tid; i < NG * D; i += 256) ps[i] = 0.f;
    __syncthreads();
    int d = tid & 31;
    int base = blockIdx.x * 1024;
    for (int i = tid >> 5; i < 1024; i += 8) {
        int n = base + i;
        if (n < NN) atomicAdd(&ps[gid[n] * D + d], g_h[n * D + d]);
    }
    __syncthreads();
    for (int i = tid; i < NG * D; i += 256) {
        float v = ps[i];
        if (v != 0.f) atomicAdd(&g_pool[i], v);
    }
}

__global__ void mlp_kernel(const float* __restrict__ Wfc1, const float* __restrict__ bfc1,
                           const float* __restrict__ Wout, const float* __restrict__ bout,
                           float* __restrict__ out) {
    int g = threadIdx.x;
    if (g >= NG) return;
    float hv[D];
#pragma unroll
    for (int k = 0; k < D; k++) hv[k] = g_pool[g * D + k];
    float h2[8];
#pragma unroll
    for (int j = 0; j < 8; j++) {
        float s = bfc1[j];
#pragma unroll
        for (int k = 0; k < D; k++) s = fmaf(hv[k], Wfc1[k * 8 + j], s);
        h2[j] = fmaxf(s, 0.f);
    }
    float o[4];
    float m = -1e30f;
#pragma unroll
    for (int j = 0; j < 4; j++) {
        float s = bout[j];
#pragma unroll
        for (int k = 0; k < 8; k++) s = fmaf(h2[k], Wout[k * 4 + j], s);
        o[j] = fmaxf(s, 0.f);
        if (o[j] > m) m = o[j];
    }
    float e[4]; float sum = 0.f;
#pragma unroll
    for (int j = 0; j < 4; j++) { e[j] = expf(o[j] - m); sum += e[j]; }
#pragma unroll
    for (int j = 0; j < 4; j++) out[g * 4 + j] = e[j] / sum;
}

// ------------------------------------------------------------------
extern "C" void kernel_launch(void* const* d_in, const int* in_sizes, int n_in,
                              void* d_out, int out_size) {
    const float* x    = (const float*)d_in[0];
    const float* Wn0  = (const float*)d_in[1];
    const float* bn0  = (const float*)d_in[2];
    const float* Ws0  = (const float*)d_in[3];
    const float* Wn   = (const float*)d_in[4];
    const float* bn   = (const float*)d_in[5];
    const float* Ws   = (const float*)d_in[6];
    const float* Wfc1 = (const float*)d_in[7];
    const float* bfc1 = (const float*)d_in[8];
    const float* Wout = (const float*)d_in[9];
    const float* bout = (const float*)d_in[10];
    const int*   src  = (const int*)d_in[11];
    const int*   dst  = (const int*)d_in[12];
    const int*   gid  = (const int*)d_in[13];
    float* out = (float*)d_out;

    zero_kernel<<<(NPAD + 255) / 256, 256>>>();
    hist_kernel<<<(NE / 4 + 255) / 256, 256>>>(dst);
    scan_all<<<1, 1024>>>();
    scatter_kernel<<<(NE / 4 + 255) / 256, 256>>>(src, dst);

    gemm0_kernel<<<(NN + 63) / 64, 64>>>(x, Wn0, Ws0);
    agg_kernel<<<(NN * 32 + 255) / 256, 256>>>(bn0);

    for (int l = 0; l < 3; l++) {
        gemm_small_kernel<<<(NN + 63) / 64, 64>>>(Wn + l * D * D, Ws + l * D * D);
        agg_kernel<<<(NN * 32 + 255) / 256, 256>>>(bn + l * D);
    }

    pool_kernel<<<(NN + 1023) / 1024, 256>>>(gid);
    mlp_kernel<<<1, 64>>>(Wfc1, bfc1, Wout, bout, out);
}

// round 8
// speedup vs baseline: 1.0555x; 1.0555x over previous
#include <cuda_runtime.h>
#include <cuda_fp16.h>
#include <math.h>

#define NN 100000
#define NE 3200000
#define NG 64
#define D 32
#define INF 128
#define NPAD 102400   // 1024 threads * 100 counters

// ---- scratch ----
__device__ __half g_rhsH[NN * D];   // fp16 gather buffer (64B rows)
__device__ float  g_self[NN * D];
__device__ float  g_h[NN * D];
__device__ float  g_pool[NG * D];
__device__ int    g_counts[NPAD];
__device__ int    g_offs[NPAD + 1];
__device__ int    g_cursor[NPAD];
__device__ int    g_csrc[NE];

// ------------------------------------------------------------------
__global__ void zero_kernel() {
    int i = blockIdx.x * blockDim.x + threadIdx.x;
    if (i < NPAD) g_counts[i] = 0;
    if (i < NG * D) g_pool[i] = 0.f;
}

__global__ void hist_kernel(const int* __restrict__ dst) {
    int i = blockIdx.x * blockDim.x + threadIdx.x;
    int b = i * 4;
    if (b < NE) {
        int4 d = *(const int4*)&dst[b];
        atomicAdd(&g_counts[d.x], 1);
        atomicAdd(&g_counts[d.y], 1);
        atomicAdd(&g_counts[d.z], 1);
        atomicAdd(&g_counts[d.w], 1);
    }
}

// single-block scan: 1024 threads x 100 contiguous counters each
__global__ void __launch_bounds__(1024) scan_all() {
    const int CH = 100;
    int tid = threadIdx.x;
    int lane = tid & 31, wid = tid >> 5;
    int base = tid * CH;
    int s = 0;
#pragma unroll
    for (int i = 0; i < CH; i += 4) {
        int4 v = *(const int4*)&g_counts[base + i];
        s += v.x + v.y + v.z + v.w;
    }
    int pre = s;
#pragma unroll
    for (int dd = 1; dd < 32; dd <<= 1) {
        int t = __shfl_up_sync(0xffffffffu, pre, dd);
        if (lane >= dd) pre += t;
    }
    __shared__ int wsum[32];
    if (lane == 31) wsum[wid] = pre;
    __syncthreads();
    if (wid == 0) {
        int v = wsum[lane];
        int p = v;
#pragma unroll
        for (int dd = 1; dd < 32; dd <<= 1) {
            int t = __shfl_up_sync(0xffffffffu, p, dd);
            if (lane >= dd) p += t;
        }
        wsum[lane] = p - v;
    }
    __syncthreads();
    int run = wsum[wid] + (pre - s);
#pragma unroll
    for (int i = 0; i < CH; i += 4) {
        int4 c = *(const int4*)&g_counts[base + i];
        int4 o;
        o.x = run; run += c.x;
        o.y = run; run += c.y;
        o.z = run; run += c.z;
        o.w = run; run += c.w;
        *(int4*)&g_offs[base + i]   = o;
        *(int4*)&g_cursor[base + i] = o;
    }
}

__global__ void scatter_kernel(const int* __restrict__ src, const int* __restrict__ dst) {
    int i = blockIdx.x * blockDim.x + threadIdx.x;
    int b = i * 4;
    if (b < NE) {
        int4 s4 = *(const int4*)&src[b];
        int4 d4 = *(const int4*)&dst[b];
        int p;
        p = atomicAdd(&g_cursor[d4.x], 1); g_csrc[p] = s4.x;
        p = atomicAdd(&g_cursor[d4.y], 1); g_csrc[p] = s4.y;
        p = atomicAdd(&g_cursor[d4.z], 1); g_csrc[p] = s4.z;
        p = atomicAdd(&g_cursor[d4.w], 1); g_csrc[p] = s4.w;
    }
}

// ------------------------------------------------------------------
// Store helper: 16 fp32 accumulators -> 16 fp16 at rhsH[n*D + c0] (two uint4 = 32B)
__device__ __forceinline__ void store_rhs_fp16(__half* dstp, const float* a) {
    __align__(16) __half2 hp[8];
#pragma unroll
    for (int j = 0; j < 8; j++)
        hp[j] = __floats2half2_rn(a[2 * j], a[2 * j + 1]);
    *(uint4*)&dstp[0] = *(uint4*)&hp[0];
    *(uint4*)&dstp[8] = *(uint4*)&hp[4];
}

// Layer 0: rhsH = fp16(x@Wn0), self = x@Ws0  (register blocked).
__global__ void __launch_bounds__(64) gemm0_kernel(const float* __restrict__ x,
                                                   const float* __restrict__ Wn0,
                                                   const float* __restrict__ Ws0) {
    __shared__ float Wsh[INF][64];
    __shared__ float xs[64][33];
    int tid = threadIdx.x;
    for (int idx = tid; idx < INF * D; idx += 64) {
        int k = idx >> 5, c = idx & 31;
        Wsh[k][c]      = Wn0[idx];
        Wsh[k][c + 32] = Ws0[idx];
    }
    int n0 = blockIdx.x * 64;
    int ng = tid >> 2, cg = tid & 3;
    int c0 = cg * 16;
    float acc[4][16];
#pragma unroll
    for (int i = 0; i < 4; i++)
#pragma unroll
        for (int j = 0; j < 16; j++) acc[i][j] = 0.f;

    for (int kt = 0; kt < 4; kt++) {
        __syncthreads();
        for (int idx = tid; idx < 64 * 32; idx += 64) {
            int nl = idx >> 5, j = idx & 31;
            int n = n0 + nl;
            xs[nl][j] = (n < NN) ? x[n * INF + kt * 32 + j] : 0.f;
        }
        __syncthreads();
#pragma unroll 4
        for (int k = 0; k < 32; k++) {
            float xv[4];
#pragma unroll
            for (int i = 0; i < 4; i++) xv[i] = xs[ng * 4 + i][k];
            const float* wrow = &Wsh[kt * 32 + k][c0];
            float4 w0 = *(const float4*)&wrow[0];
            float4 w1 = *(const float4*)&wrow[4];
            float4 w2 = *(const float4*)&wrow[8];
            float4 w3 = *(const float4*)&wrow[12];
#pragma unroll
            for (int i = 0; i < 4; i++) {
                float xi = xv[i];
                acc[i][0]  = fmaf(xi, w0.x, acc[i][0]);
                acc[i][1]  = fmaf(xi, w0.y, acc[i][1]);
                acc[i][2]  = fmaf(xi, w0.z, acc[i][2]);
                acc[i][3]  = fmaf(xi, w0.w, acc[i][3]);
                acc[i][4]  = fmaf(xi, w1.x, acc[i][4]);
                acc[i][5]  = fmaf(xi, w1.y, acc[i][5]);
                acc[i][6]  = fmaf(xi, w1.z, acc[i][6]);
                acc[i][7]  = fmaf(xi, w1.w, acc[i][7]);
                acc[i][8]  = fmaf(xi, w2.x, acc[i][8]);
                acc[i][9]  = fmaf(xi, w2.y, acc[i][9]);
                acc[i][10] = fmaf(xi, w2.z, acc[i][10]);
                acc[i][11] = fmaf(xi, w2.w, acc[i][11]);
                acc[i][12] = fmaf(xi, w3.x, acc[i][12]);
                acc[i][13] = fmaf(xi, w3.y, acc[i][13]);
                acc[i][14] = fmaf(xi, w3.z, acc[i][14]);
                acc[i][15] = fmaf(xi, w3.w, acc[i][15]);
            }
        }
    }
#pragma unroll
    for (int i = 0; i < 4; i++) {
        int n = n0 + ng * 4 + i;
        if (n >= NN) break;
        if (cg < 2) {
            store_rhs_fp16(&g_rhsH[n * D + c0], acc[i]);
        } else {
            float* dstp = &g_self[n * D + (c0 - 32)];
#pragma unroll
            for (int j = 0; j < 4; j++) {
                float4 f = make_float4(acc[i][4 * j], acc[i][4 * j + 1],
                                       acc[i][4 * j + 2], acc[i][4 * j + 3]);
                *(float4*)&dstp[4 * j] = f;
            }
        }
    }
}

// Layers 1..3: rhsH = fp16(h@Wn_l), self = h@Ws_l  (register blocked, K=32).
__global__ void __launch_bounds__(64) gemm_small_kernel(const float* __restrict__ Wn_l,
                                                        const float* __restrict__ Ws_l) {
    __shared__ float Wsh[D][64];
    __shared__ float xs[64][33];
    int tid = threadIdx.x;
    for (int idx = tid; idx < D * D; idx += 64) {
        int k = idx >> 5, c = idx & 31;
        Wsh[k][c]      = Wn_l[idx];
        Wsh[k][c + 32] = Ws_l[idx];
    }
    int n0 = blockIdx.x * 64;
    for (int idx = tid; idx < 64 * 32; idx += 64) {
        int nl = idx >> 5, j = idx & 31;
        int n = n0 + nl;
        xs[nl][j] = (n < NN) ? g_h[n * D + j] : 0.f;
    }
    __syncthreads();
    int ng = tid >> 2, cg = tid & 3;
    int c0 = cg * 16;
    float acc[4][16];
#pragma unroll
    for (int i = 0; i < 4; i++)
#pragma unroll
        for (int j = 0; j < 16; j++) acc[i][j] = 0.f;

#pragma unroll 4
    for (int k = 0; k < 32; k++) {
        float xv[4];
#pragma unroll
        for (int i = 0; i < 4; i++) xv[i] = xs[ng * 4 + i][k];
        const float* wrow = &Wsh[k][c0];
        float4 w0 = *(const float4*)&wrow[0];
        float4 w1 = *(const float4*)&wrow[4];
        float4 w2 = *(const float4*)&wrow[8];
        float4 w3 = *(const float4*)&wrow[12];
#pragma unroll
        for (int i = 0; i < 4; i++) {
            float xi = xv[i];
            acc[i][0]  = fmaf(xi, w0.x, acc[i][0]);
            acc[i][1]  = fmaf(xi, w0.y, acc[i][1]);
            acc[i][2]  = fmaf(xi, w0.z, acc[i][2]);
            acc[i][3]  = fmaf(xi, w0.w, acc[i][3]);
            acc[i][4]  = fmaf(xi, w1.x, acc[i][4]);
            acc[i][5]  = fmaf(xi, w1.y, acc[i][5]);
            acc[i][6]  = fmaf(xi, w1.z, acc[i][6]);
            acc[i][7]  = fmaf(xi, w1.w, acc[i][7]);
            acc[i][8]  = fmaf(xi, w2.x, acc[i][8]);
            acc[i][9]  = fmaf(xi, w2.y, acc[i][9]);
            acc[i][10] = fmaf(xi, w2.z, acc[i][10]);
            acc[i][11] = fmaf(xi, w2.w, acc[i][11]);
            acc[i][12] = fmaf(xi, w3.x, acc[i][12]);
            acc[i][13] = fmaf(xi, w3.y, acc[i][13]);
            acc[i][14] = fmaf(xi, w3.z, acc[i][14]);
            acc[i][15] = fmaf(xi, w3.w, acc[i][15]);
        }
    }
#pragma unroll
    for (int i = 0; i < 4; i++) {
        int n = n0 + ng * 4 + i;
        if (n >= NN) break;
        if (cg < 2) {
            store_rhs_fp16(&g_rhsH[n * D + c0], acc[i]);
        } else {
            float* dstp = &g_self[n * D + (c0 - 32)];
#pragma unroll
            for (int j = 0; j < 4; j++) {
                float4 f = make_float4(acc[i][4 * j], acc[i][4 * j + 1],
                                       acc[i][4 * j + 2], acc[i][4 * j + 3]);
                *(float4*)&dstp[4 * j] = f;
            }
        }
    }
}

// ------------------------------------------------------------------
// Vectorized aggregation: warp per node; 8 edges per warp-LDG.
// Lane role: eg = lane>>2 (edge slot 0..7), q = lane&3 (dims 8q..8q+7 as uint4).
__device__ __forceinline__ void acc8(uint4 v, float* f) {
    const __half2* h = (const __half2*)&v;
#pragma unroll
    for (int j = 0; j < 4; j++) {
        float2 t = __half22float2(h[j]);
        f[2 * j]     += t.x;
        f[2 * j + 1] += t.y;
    }
}

__global__ void __launch_bounds__(256) agg_kernel(const float* __restrict__ bn) {
    int tid = threadIdx.x;
    int w = (blockIdx.x * blockDim.x + tid) >> 5;
    if (w >= NN) return;
    int lane = tid & 31;
    int eg = lane >> 2, q = lane & 3;
    const uint4* __restrict__ rhs4 = (const uint4*)g_rhsH;   // 4 uint4 per row

    int beg = g_offs[w], end = g_offs[w + 1];
    float f[8];
#pragma unroll
    for (int j = 0; j < 8; j++) f[j] = 0.f;

    int e = beg;
    // 2x unrolled: 16 edges in flight (2 idx LDG + 2 gather LDG)
    while (e + 16 <= end) {
        int s0 = g_csrc[e + eg];
        int s1 = g_csrc[e + 8 + eg];
        uint4 v0 = rhs4[s0 * 4 + q];
        uint4 v1 = rhs4[s1 * 4 + q];
        acc8(v0, f);
        acc8(v1, f);
        e += 16;
    }
    while (e + 8 <= end) {
        int s = g_csrc[e + eg];
        uint4 v = rhs4[s * 4 + q];
        acc8(v, f);
        e += 8;
    }
    int rem = end - e;
    if (eg < rem) {
        int s = g_csrc[e + eg];
        uint4 v = rhs4[s * 4 + q];
        acc8(v, f);
    }

    // reduce across the 8 edge slots (lanes differing in bits 2..4)
#pragma unroll
    for (int j = 0; j < 8; j++) {
        f[j] += __shfl_xor_sync(0xffffffffu, f[j], 4);
        f[j] += __shfl_xor_sync(0xffffffffu, f[j], 8);
        f[j] += __shfl_xor_sync(0xffffffffu, f[j], 16);
    }

    // lanes 0..3: q covers dims 8q..8q+7; apply self + bias + relu, store
    if (lane < 4) {
        int base = w * D + 8 * lane;
        float4 s0 = *(const float4*)&g_self[base];
        float4 s1 = *(const float4*)&g_self[base + 4];
        float4 b0 = *(const float4*)&bn[8 * lane];
        float4 b1 = *(const float4*)&bn[8 * lane + 4];
        float4 o0, o1;
        o0.x = fmaxf(f[0] + s0.x + b0.x, 0.f);
        o0.y = fmaxf(f[1] + s0.y + b0.y, 0.f);
        o0.z = fmaxf(f[2] + s0.z + b0.z, 0.f);
        o0.w = fmaxf(f[3] + s0.w + b0.w, 0.f);
        o1.x = fmaxf(f[4] + s1.x + b1.x, 0.f);
        o1.y = fmaxf(f[5] + s1.y + b1.y, 0.f);
        o1.z = fmaxf(f[6] + s1.z + b1.z, 0.f);
        o1.w = fmaxf(f[7] + s1.w + b1.w, 0.f);
        *(float4*)&g_h[base]     = o0;
        *(float4*)&g_h[base + 4] = o1;
    }
}

// ------------------------------------------------------------------
__global__ void __launch_bounds__(256) pool_kernel(const int* __restrict__ gid) {
    __shared__ float ps[NG * D];
    int tid = threadIdx.x;
    for (int i = tid; i < NG * D; i += 256) ps[i] = 0.f;
    __syncthreads();
    int d = tid & 31;
    int base = blockIdx.x * 1024;
    for (int i = tid >> 5; i < 1024; i += 8) {
        int n = base + i;
        if (n < NN) atomicAdd(&ps[gid[n] * D + d], g_h[n * D + d]);
    }
    __syncthreads();
    for (int i = tid; i < NG * D; i += 256) {
        float v = ps[i];
        if (v != 0.f) atomicAdd(&g_pool[i], v);
    }
}

__global__ void mlp_kernel(const float* __restrict__ Wfc1, const float* __restrict__ bfc1,
                           const float* __restrict__ Wout, const float* __restrict__ bout,
                           float* __restrict__ out) {
    int g = threadIdx.x;
    if (g >= NG) return;
    float hv[D];
#pragma unroll
    for (int k = 0; k < D; k++) hv[k] = g_pool[g * D + k];
    float h2[8];
#pragma unroll
    for (int j = 0; j < 8; j++) {
        float s = bfc1[j];
#pragma unroll
        for (int k = 0; k < D; k++) s = fmaf(hv[k], Wfc1[k * 8 + j], s);
        h2[j] = fmaxf(s, 0.f);
    }
    float o[4];
    float m = -1e30f;
#pragma unroll
    for (int j = 0; j < 4; j++) {
        float s = bout[j];
#pragma unroll
        for (int k = 0; k < 8; k++) s = fmaf(h2[k], Wout[k * 4 + j], s);
        o[j] = fmaxf(s, 0.f);
        if (o[j] > m) m = o[j];
    }
    float e[4]; float sum = 0.f;
#pragma unroll
    for (int j = 0; j < 4; j++) { e[j] = expf(o[j] - m); sum += e[j]; }
#pragma unroll
    for (int j = 0; j < 4; j++) out[g * 4 + j] = e[j] / sum;
}

// ------------------------------------------------------------------
extern "C" void kernel_launch(void* const* d_in, const int* in_sizes, int n_in,
                              void* d_out, int out_size) {
    const float* x    = (const float*)d_in[0];
    const float* Wn0  = (const float*)d_in[1];
    const float* bn0  = (const float*)d_in[2];
    const float* Ws0  = (const float*)d_in[3];
    const float* Wn   = (const float*)d_in[4];
    const float* bn   = (const float*)d_in[5];
    const float* Ws   = (const float*)d_in[6];
    const float* Wfc1 = (const float*)d_in[7];
    const float* bfc1 = (const float*)d_in[8];
    const float* Wout = (const float*)d_in[9];
    const float* bout = (const float*)d_in[10];
    const int*   src  = (const int*)d_in[11];
    const int*   dst  = (const int*)d_in[12];
    const int*   gid  = (const int*)d_in[13];
    float* out = (float*)d_out;

    zero_kernel<<<(NPAD + 255) / 256, 256>>>();
    hist_kernel<<<(NE / 4 + 255) / 256, 256>>>(dst);
    scan_all<<<1, 1024>>>();
    scatter_kernel<<<(NE / 4 + 255) / 256, 256>>>(src, dst);

    gemm0_kernel<<<(NN + 63) / 64, 64>>>(x, Wn0, Ws0);
    agg_kernel<<<(NN * 32 + 255) / 256, 256>>>(bn0);

    for (int l = 0; l < 3; l++) {
        gemm_small_kernel<<<(NN + 63) / 64, 64>>>(Wn + l * D * D, Ws + l * D * D);
        agg_kernel<<<(NN * 32 + 255) / 256, 256>>>(bn + l * D);
    }

    pool_kernel<<<(NN + 1023) / 1024, 256>>>(gid);
    mlp_kernel<<<1, 64>>>(Wfc1, bfc1, Wout, bout, out);
}